// round 2
// baseline (speedup 1.0000x reference)
#include <cuda_runtime.h>

#define HID 256
#define G3 768
#define NB 8192
#define SEQ 49
#define TLEN 50
#define VOCAB 148
#define LATENT 32

#define RB 16      // rows per CTA in step/proj kernels
#define STRD 18    // padded transposed-tile stride (keeps 8B alignment, breaks bank conflicts)

typedef unsigned long long ull;

// ---- scratch (__device__ globals: allocation-free) ----
__device__ float g_h0[NB * HID];
__device__ float g_h1[NB * HID];
__device__ float g_y[(size_t)NB * SEQ * HID];
__device__ float g_G0[VOCAB * G3];
__device__ float4 g_Whh0p[HID * HID];   // [k][j] = (w_r, w_z, w_n, 0)
__device__ float4 g_Wih1p[HID * HID];
__device__ float4 g_Whh1p[HID * HID];
__device__ float g_W1t[HID * HID];      // [k][o]
__device__ float g_W2t[HID * VOCAB];    // [k][v]

__device__ __forceinline__ float sigf(float x) { return 1.f / (1.f + expf(-x)); }

__device__ __forceinline__ ull pack2(float lo, float hi) {
    ull r; asm("mov.b64 %0, {%1,%2};" : "=l"(r) : "f"(lo), "f"(hi)); return r;
}
__device__ __forceinline__ void unpack2(ull v, float& lo, float& hi) {
    asm("mov.b64 {%0,%1}, %2;" : "=f"(lo), "=f"(hi) : "l"(v));
}
__device__ __forceinline__ void fma2(ull& acc, ull a, ull b) {
    asm("fma.rn.f32x2 %0, %1, %2, %0;" : "+l"(acc) : "l"(a), "l"(b));
}

// ---- transpose W (R x C row-major) -> Wt (C x R row-major) for W1 / W2 ----
__global__ void transpose_sel(const float* __restrict__ W, int R, int C, int sel) {
    __shared__ float tile[32][33];
    float* Wt = (sel == 3) ? g_W1t : g_W2t;
    int c = blockIdx.x * 32 + threadIdx.x;
    int r = blockIdx.y * 32 + threadIdx.y;
    if (r < R && c < C) tile[threadIdx.y][threadIdx.x] = W[r * C + c];
    __syncthreads();
    int cc = blockIdx.x * 32 + threadIdx.y;
    int rr = blockIdx.y * 32 + threadIdx.x;
    if (cc < C && rr < R) Wt[cc * R + rr] = tile[threadIdx.x][threadIdx.y];
}

// ---- pack GRU weight (768x256 row-major) into gate-interleaved [k][j] float4 ----
__global__ void packW_k(const float* __restrict__ W, int sel) {
    float4* dst = (sel == 0) ? g_Whh0p : (sel == 1) ? g_Wih1p : g_Whh1p;
    int j = threadIdx.x;
    int k = blockIdx.x;
    float4 v;
    v.x = W[(size_t)(0 * HID + j) * HID + k];
    v.y = W[(size_t)(1 * HID + j) * HID + k];
    v.z = W[(size_t)(2 * HID + j) * HID + k];
    v.w = 0.f;
    dst[k * HID + j] = v;
}

// ---- h init: h[b, 2*HID] = z @ W_lat^T + b_lat ----
__global__ void hinit_k(const float* __restrict__ z, const float* __restrict__ Wlat,
                        const float* __restrict__ blat) {
    int b = blockIdx.x;
    int j = blockIdx.y * blockDim.x + threadIdx.x;  // 0..511
    __shared__ float zs[LATENT];
    if (threadIdx.x < LATENT) zs[threadIdx.x] = z[b * LATENT + threadIdx.x];
    __syncthreads();
    float acc = blat[j];
    const float* w = Wlat + (size_t)j * LATENT;
#pragma unroll
    for (int k = 0; k < LATENT; k++) acc = fmaf(zs[k], w[k], acc);
    if (j < HID) g_h0[(size_t)b * HID + j] = acc;
    else         g_h1[(size_t)b * HID + (j - HID)] = acc;
}

// ---- G0[v, 768] = emb[v] @ W_ih0^T + b_ih0  (teacher-forced input gates) ----
__global__ void g0_k(const float* __restrict__ emb, const float* __restrict__ Wih0,
                     const float* __restrict__ bih0) {
    int v = blockIdx.x;
    int g = blockIdx.y * blockDim.x + threadIdx.x;  // 0..767
    __shared__ float es[HID];
    es[threadIdx.x] = emb[v * HID + threadIdx.x];
    __syncthreads();
    float acc = bih0[g];
    const float* w = Wih0 + (size_t)g * HID;
#pragma unroll 4
    for (int k = 0; k < HID; k++) acc = fmaf(es[k], w[k], acc);
    g_G0[v * G3 + g] = acc;
}

// ---- one GRU timestep: both layers, packed f32x2 FMAs ----
__global__ __launch_bounds__(256, 1) void step_k(const int* __restrict__ tt,
                                                 const float* __restrict__ bhh0,
                                                 const float* __restrict__ bih1,
                                                 const float* __restrict__ bhh1, int t) {
    __shared__ float h0t[HID * STRD];
    __shared__ float h1t[HID * STRD];
    const int j = threadIdx.x;
    const int r0 = blockIdx.x * RB;

    // load transposed tiles: h*t[k*STRD + r] = h[r][k]
#pragma unroll
    for (int r = 0; r < RB; r++) {
        h0t[j * STRD + r] = g_h0[(size_t)(r0 + r) * HID + j];
        h1t[j * STRD + r] = g_h1[(size_t)(r0 + r) * HID + j];
    }
    __syncthreads();

    // ================= layer 0: gh0 = h0 @ W_hh0^T =================
    ull ar[8], az[8], an[8];
    {
        float br = bhh0[j], bz = bhh0[HID + j], bn = bhh0[2 * HID + j];
        ull pr = pack2(br, br), pz = pack2(bz, bz), pn = pack2(bn, bn);
#pragma unroll
        for (int p = 0; p < 8; p++) { ar[p] = pr; az[p] = pz; an[p] = pn; }
    }
#pragma unroll 2
    for (int k = 0; k < HID; k++) {
        float4 w = g_Whh0p[k * HID + j];
        ull w0 = pack2(w.x, w.x), w1 = pack2(w.y, w.y), w2 = pack2(w.z, w.z);
        const ull* hp = (const ull*)(h0t + k * STRD);
#pragma unroll
        for (int p = 0; p < 8; p++) {
            ull h2 = hp[p];
            fma2(ar[p], h2, w0);
            fma2(az[p], h2, w1);
            fma2(an[p], h2, w2);
        }
    }
    float hn[RB];
#pragma unroll
    for (int p = 0; p < 8; p++) {
        float a0, a1, z0, z1, n0, n1;
        unpack2(ar[p], a0, a1);
        unpack2(az[p], z0, z1);
        unpack2(an[p], n0, n1);
        int b0 = r0 + 2 * p;
        int tk0 = t ? tt[b0 * TLEN + t] : 1;
        int tk1 = t ? tt[(b0 + 1) * TLEN + t] : 1;
        const float* gA = g_G0 + tk0 * G3;
        const float* gB = g_G0 + tk1 * G3;
        float rg = sigf(gA[j] + a0);
        float zg = sigf(gA[HID + j] + z0);
        float nn = tanhf(gA[2 * HID + j] + rg * n0);
        hn[2 * p] = (1.f - zg) * nn + zg * h0t[j * STRD + 2 * p];
        rg = sigf(gB[j] + a1);
        zg = sigf(gB[HID + j] + z1);
        nn = tanhf(gB[2 * HID + j] + rg * n1);
        hn[2 * p + 1] = (1.f - zg) * nn + zg * h0t[j * STRD + 2 * p + 1];
    }
    __syncthreads();
#pragma unroll
    for (int r = 0; r < RB; r++) {
        h0t[j * STRD + r] = hn[r];
        g_h0[(size_t)(r0 + r) * HID + j] = hn[r];
    }
    __syncthreads();

    // ====== layer 1: gi1 = h0n @ W_ih1^T, gh1 = h1 @ W_hh1^T ======
    ull air[8], aiz[8], ain[8], ahr[8], ahz[8], ahn[8];
    {
        float b0 = bih1[j], b1v = bih1[HID + j], b2v = bih1[2 * HID + j];
        float c0 = bhh1[j], c1 = bhh1[HID + j], c2 = bhh1[2 * HID + j];
        ull p0 = pack2(b0, b0), p1 = pack2(b1v, b1v), p2 = pack2(b2v, b2v);
        ull q0 = pack2(c0, c0), q1 = pack2(c1, c1), q2 = pack2(c2, c2);
#pragma unroll
        for (int p = 0; p < 8; p++) {
            air[p] = p0; aiz[p] = p1; ain[p] = p2;
            ahr[p] = q0; ahz[p] = q1; ahn[p] = q2;
        }
    }
#pragma unroll 1
    for (int k = 0; k < HID; k++) {
        float4 wi = g_Wih1p[k * HID + j];
        float4 wh = g_Whh1p[k * HID + j];
        ull i0 = pack2(wi.x, wi.x), i1 = pack2(wi.y, wi.y), i2 = pack2(wi.z, wi.z);
        ull m0 = pack2(wh.x, wh.x), m1 = pack2(wh.y, wh.y), m2 = pack2(wh.z, wh.z);
        const ull* xp = (const ull*)(h0t + k * STRD);
        const ull* hp = (const ull*)(h1t + k * STRD);
#pragma unroll
        for (int p = 0; p < 8; p++) {
            ull x2 = xp[p];
            ull h2 = hp[p];
            fma2(air[p], x2, i0);
            fma2(aiz[p], x2, i1);
            fma2(ain[p], x2, i2);
            fma2(ahr[p], h2, m0);
            fma2(ahz[p], h2, m1);
            fma2(ahn[p], h2, m2);
        }
    }
#pragma unroll
    for (int p = 0; p < 8; p++) {
        float i0a, i0b, i1a, i1b, i2a, i2b, m0a, m0b, m1a, m1b, m2a, m2b;
        unpack2(air[p], i0a, i0b);
        unpack2(aiz[p], i1a, i1b);
        unpack2(ain[p], i2a, i2b);
        unpack2(ahr[p], m0a, m0b);
        unpack2(ahz[p], m1a, m1b);
        unpack2(ahn[p], m2a, m2b);
        int r = 2 * p;
        {
            float rg = sigf(i0a + m0a);
            float zg = sigf(i1a + m1a);
            float nn = tanhf(i2a + rg * m2a);
            float hv = (1.f - zg) * nn + zg * h1t[j * STRD + r];
            size_t b = r0 + r;
            g_h1[b * HID + j] = hv;
            g_y[(b * SEQ + t) * HID + j] = hv;
        }
        {
            float rg = sigf(i0b + m0b);
            float zg = sigf(i1b + m1b);
            float nn = tanhf(i2b + rg * m2b);
            float hv = (1.f - zg) * nn + zg * h1t[j * STRD + r + 1];
            size_t b = r0 + r + 1;
            g_h1[b * HID + j] = hv;
            g_y[(b * SEQ + t) * HID + j] = hv;
        }
    }
}

// ---- fused projection: logits = relu(y @ W1^T + b1) @ W2^T + b2 ----
__global__ __launch_bounds__(256, 1) void proj_k(const float* __restrict__ b1,
                                                 const float* __restrict__ b2,
                                                 float* __restrict__ out) {
    __shared__ float yt[HID * STRD];
    __shared__ float ht[HID * STRD];
    const int j = threadIdx.x;
    const size_t row0 = (size_t)blockIdx.x * RB;

#pragma unroll
    for (int r = 0; r < RB; r++) yt[j * STRD + r] = g_y[(row0 + r) * HID + j];
    __syncthreads();

    // stage 1: hidden = relu(y @ W1^T + b1)
    {
        ull a[8];
        float bb = b1[j];
        ull pb = pack2(bb, bb);
#pragma unroll
        for (int p = 0; p < 8; p++) a[p] = pb;
#pragma unroll 2
        for (int k = 0; k < HID; k++) {
            float w = g_W1t[k * HID + j];
            ull w2 = pack2(w, w);
            const ull* yp = (const ull*)(yt + k * STRD);
#pragma unroll
            for (int p = 0; p < 8; p++) fma2(a[p], yp[p], w2);
        }
        float hd[RB];
#pragma unroll
        for (int p = 0; p < 8; p++) {
            float lo, hi;
            unpack2(a[p], lo, hi);
            hd[2 * p] = fmaxf(lo, 0.f);
            hd[2 * p + 1] = fmaxf(hi, 0.f);
        }
#pragma unroll
        for (int r = 0; r < RB; r++) ht[j * STRD + r] = hd[r];
    }
    __syncthreads();

    // stage 2: logits = hidden @ W2^T + b2  (VOCAB=148 columns)
    if (j < VOCAB) {
        ull a[8];
        float bb = b2[j];
        ull pb = pack2(bb, bb);
#pragma unroll
        for (int p = 0; p < 8; p++) a[p] = pb;
#pragma unroll 2
        for (int k = 0; k < HID; k++) {
            float w = g_W2t[k * VOCAB + j];
            ull w2 = pack2(w, w);
            const ull* hp = (const ull*)(ht + k * STRD);
#pragma unroll
            for (int p = 0; p < 8; p++) fma2(a[p], hp[p], w2);
        }
#pragma unroll
        for (int p = 0; p < 8; p++) {
            float lo, hi;
            unpack2(a[p], lo, hi);
            out[(row0 + 2 * p) * VOCAB + j] = lo;
            out[(row0 + 2 * p + 1) * VOCAB + j] = hi;
        }
    }
}

// ---- generated = float(target_tokens[:, 1:]) ----
__global__ void gen_k(const int* __restrict__ tt, float* __restrict__ outg) {
    int i = blockIdx.x * blockDim.x + threadIdx.x;
    if (i < NB * SEQ) {
        int b = i / SEQ, s = i % SEQ;
        outg[i] = (float)tt[b * TLEN + 1 + s];
    }
}

extern "C" void kernel_launch(void* const* d_in, const int* in_sizes, int n_in,
                              void* d_out, int out_size) {
    const float* z    = (const float*)d_in[0];
    const int*   tt   = (const int*)  d_in[1];
    const float* emb  = (const float*)d_in[2];
    const float* Wlat = (const float*)d_in[3];
    const float* blat = (const float*)d_in[4];
    const float* Wih0 = (const float*)d_in[5];
    const float* Whh0 = (const float*)d_in[6];
    const float* bih0 = (const float*)d_in[7];
    const float* bhh0 = (const float*)d_in[8];
    const float* Wih1 = (const float*)d_in[9];
    const float* Whh1 = (const float*)d_in[10];
    const float* bih1 = (const float*)d_in[11];
    const float* bhh1 = (const float*)d_in[12];
    const float* W1   = (const float*)d_in[13];
    const float* b1   = (const float*)d_in[14];
    const float* W2   = (const float*)d_in[15];
    const float* b2   = (const float*)d_in[16];
    float* out = (float*)d_out;

    dim3 tb(32, 32);
    transpose_sel<<<dim3(8, 8), tb>>>(W1, HID, HID, 3);
    transpose_sel<<<dim3(8, 5), tb>>>(W2, VOCAB, HID, 4);

    packW_k<<<HID, HID>>>(Whh0, 0);
    packW_k<<<HID, HID>>>(Wih1, 1);
    packW_k<<<HID, HID>>>(Whh1, 2);

    hinit_k<<<dim3(NB, 2), 256>>>(z, Wlat, blat);
    g0_k<<<dim3(VOCAB, 3), 256>>>(emb, Wih0, bih0);

    for (int t = 0; t < SEQ; t++) {
        step_k<<<NB / RB, 256>>>(tt, bhh0, bih1, bhh1, t);
    }

    proj_k<<<(NB * SEQ) / RB, 256>>>(b1, b2, out);
    gen_k<<<(NB * SEQ + 255) / 256, 256>>>(tt, out + (size_t)NB * SEQ * VOCAB);
}

// round 3
// speedup vs baseline: 1.2264x; 1.2264x over previous
#include <cuda_runtime.h>

#define HID 256
#define G3 768
#define NB 8192
#define SEQ 49
#define TLEN 50
#define VOCAB 148
#define LATENT 32

#define RB 28        // rows per CTA (recurrence)
#define STRD 32      // padded floats per k-row in SMEM tiles (8 quads x 4)
#define GRID_G 293   // ceil(8192/28)
#define PRB 32       // rows per CTA (projection)

typedef unsigned long long ull;

// ---- scratch (__device__ globals: allocation-free) ----
__device__ float g_h0[NB * HID];
__device__ float g_h1[NB * HID];
__device__ float g_y[(size_t)NB * SEQ * HID];
__device__ float g_G0[VOCAB * G3];
__device__ float4 g_Whh0p[HID * HID];       // [k][j] = (w_r, w_z, w_n, 0)
__device__ float4 g_Wc1[2 * HID * HID];     // [0:256)=Wih1 packed, [256:512)=Whh1 packed
__device__ float g_W1t[HID * HID];          // [k][o]
__device__ float g_W2t[HID * VOCAB];        // [k][v]

__device__ __forceinline__ float sigf(float x) { return 1.f / (1.f + expf(-x)); }

__device__ __forceinline__ ull pack2(float lo, float hi) {
    ull r; asm("mov.b64 %0, {%1,%2};" : "=l"(r) : "f"(lo), "f"(hi)); return r;
}
__device__ __forceinline__ void unpack2(ull v, float& lo, float& hi) {
    asm("mov.b64 {%0,%1}, %2;" : "=f"(lo), "=f"(hi) : "l"(v));
}
__device__ __forceinline__ void fma2(ull& acc, ull a, ull b) {
    asm("fma.rn.f32x2 %0, %1, %2, %0;" : "+l"(acc) : "l"(a), "l"(b));
}

// ============================================================
// Prep kernels (exactly 5 launches before gru_k so ncu -s 5 hits gru_k)
// ============================================================

// 1) h init: h[b, 2*HID] = z @ W_lat^T + b_lat
__global__ void hinit_k(const float* __restrict__ z, const float* __restrict__ Wlat,
                        const float* __restrict__ blat) {
    int b = blockIdx.x;
    int j = blockIdx.y * blockDim.x + threadIdx.x;  // 0..511
    __shared__ float zs[LATENT];
    if (threadIdx.x < LATENT) zs[threadIdx.x] = z[b * LATENT + threadIdx.x];
    __syncthreads();
    float acc = blat[j];
    const float* w = Wlat + (size_t)j * LATENT;
#pragma unroll
    for (int k = 0; k < LATENT; k++) acc = fmaf(zs[k], w[k], acc);
    if (j < HID) g_h0[(size_t)b * HID + j] = acc;
    else         g_h1[(size_t)b * HID + (j - HID)] = acc;
}

// 2) G0[v, 768] = emb[v] @ W_ih0^T + b_ih0
__global__ void g0_k(const float* __restrict__ emb, const float* __restrict__ Wih0,
                     const float* __restrict__ bih0) {
    int v = blockIdx.x;
    int g = blockIdx.y * blockDim.x + threadIdx.x;  // 0..767
    __shared__ float es[HID];
    es[threadIdx.x] = emb[v * HID + threadIdx.x];
    __syncthreads();
    float acc = bih0[g];
    const float* w = Wih0 + (size_t)g * HID;
#pragma unroll 4
    for (int k = 0; k < HID; k++) acc = fmaf(es[k], w[k], acc);
    g_G0[v * G3 + g] = acc;
}

// 3) transpose W1 -> W1t [k][o] and W2 -> W2t [k][v]
__global__ void trW12_k(const float* __restrict__ W1, const float* __restrict__ W2) {
    int k = blockIdx.x;
    int j = threadIdx.x;
    if (blockIdx.y == 0)      g_W1t[k * HID + j]   = W1[(size_t)j * HID + k];
    else if (j < VOCAB)       g_W2t[k * VOCAB + j] = W2[(size_t)j * HID + k];
}

// 4) pack Whh0 gate-interleaved [k][j]
__global__ void packW0_k(const float* __restrict__ W) {
    int k = blockIdx.x, j = threadIdx.x;
    float4 v;
    v.x = W[(size_t)(0 * HID + j) * HID + k];
    v.y = W[(size_t)(1 * HID + j) * HID + k];
    v.z = W[(size_t)(2 * HID + j) * HID + k];
    v.w = 0.f;
    g_Whh0p[k * HID + j] = v;
}

// 5) pack Wih1 (k'<256) and Whh1 (k'>=256)
__global__ void packWc1_k(const float* __restrict__ Wih1, const float* __restrict__ Whh1) {
    int kp = blockIdx.x;            // 0..511
    int j = threadIdx.x;
    const float* W = (kp < HID) ? Wih1 : Whh1;
    int k = kp & (HID - 1);
    float4 v;
    v.x = W[(size_t)(0 * HID + j) * HID + k];
    v.y = W[(size_t)(1 * HID + j) * HID + k];
    v.z = W[(size_t)(2 * HID + j) * HID + k];
    v.w = 0.f;
    g_Wc1[kp * HID + j] = v;
}

// ============================================================
// Persistent GRU recurrence
// ============================================================

// 3-gate row-blocked GEMM fragment: NQ quads (4 rows each) starting at quad qb.
// A/B/C are 2*NQ packed accumulators; Wj points at packed weights offset by column j.
template<int NQ>
__device__ __forceinline__ void gemm3(ull* A, ull* B, ull* C,
                                      const float4* __restrict__ Wj,
                                      const float* __restrict__ tile, int qb) {
#pragma unroll 2
    for (int k = 0; k < HID; k++) {
        float4 w = Wj[(size_t)k * HID];
        ull w0 = pack2(w.x, w.x), w1 = pack2(w.y, w.y), w2 = pack2(w.z, w.z);
        const ulonglong2* hp = (const ulonglong2*)(tile + k * STRD) + qb;
#pragma unroll
        for (int q = 0; q < NQ; q++) {
            ulonglong2 h4 = hp[q];
            fma2(A[2 * q], h4.x, w0); fma2(A[2 * q + 1], h4.y, w0);
            fma2(B[2 * q], h4.x, w1); fma2(B[2 * q + 1], h4.y, w1);
            fma2(C[2 * q], h4.x, w2); fma2(C[2 * q + 1], h4.y, w2);
        }
    }
}

__global__ void __launch_bounds__(512) gru_k(const int* __restrict__ tt,
                                             const float* __restrict__ bhh0,
                                             const float* __restrict__ bih1,
                                             const float* __restrict__ bhh1) {
    extern __shared__ float sm[];
    float* h0t = sm;                 // [k=256][STRD] transposed tile
    float* h1t = sm + HID * STRD;
    __shared__ int toks[RB];

    const int tid = threadIdx.x;
    const int j   = tid & (HID - 1); // column 0..255
    const int rh  = tid >> 8;        // 0: quads 0..3 (rows 0..15), 1: quads 4..6 (rows 16..27)
    const int r0  = blockIdx.x * RB;
    const int qb  = rh * 4;
    const int nu  = rh ? 6 : 8;      // packed accumulators in use

    // biases (duplicated into packed pairs), fixed across t
    ull b0r = pack2(bhh0[j], bhh0[j]);
    ull b0z = pack2(bhh0[HID + j], bhh0[HID + j]);
    ull b0n = pack2(bhh0[2 * HID + j], bhh0[2 * HID + j]);
    float t1r = bih1[j] + bhh1[j];
    float t1z = bih1[HID + j] + bhh1[HID + j];
    ull b1r  = pack2(t1r, t1r);
    ull b1z  = pack2(t1z, t1z);
    ull b1in = pack2(bih1[2 * HID + j], bih1[2 * HID + j]);
    ull b1hn = pack2(bhh1[2 * HID + j], bhh1[2 * HID + j]);

    // load initial h tiles (coalesced global reads)
    for (int idx = tid; idx < RB * HID; idx += 512) {
        int r = idx >> 8, c = idx & (HID - 1);
        int bc = min(r0 + r, NB - 1);
        h0t[c * STRD + r] = g_h0[(size_t)bc * HID + c];
        h1t[c * STRD + r] = g_h1[(size_t)bc * HID + c];
    }
    __syncthreads();

    ull A[8], B[8], C[8], D[8];

    for (int t = 0; t < SEQ; t++) {
        if (tid < RB) {
            int b = min(r0 + tid, NB - 1);
            toks[tid] = t ? tt[b * TLEN + t] : 1;
        }

        // ---------- layer 0: gh0 = h0 @ W_hh0^T ----------
#pragma unroll
        for (int u = 0; u < 8; u++) { A[u] = b0r; B[u] = b0z; C[u] = b0n; }
        if (rh == 0) gemm3<4>(A, B, C, g_Whh0p + j, h0t, 0);
        else         gemm3<3>(A, B, C, g_Whh0p + j, h0t, 4);
        __syncthreads();   // all reads of old h0t done; toks visible

        // epilogue 0 (gather gi0 from G0, update h0 tile in place)
#pragma unroll
        for (int u = 0; u < 8; u++) {
            if (u >= nu) break;
            float a0, a1, z0, z1, n0, n1;
            unpack2(A[u], a0, a1); unpack2(B[u], z0, z1); unpack2(C[u], n0, n1);
            int r = qb * 4 + 2 * u;
            {
                const float* gA = g_G0 + (size_t)toks[r] * G3 + j;
                float rg = sigf(gA[0] + a0), zg = sigf(gA[HID] + z0);
                float nn = tanhf(gA[2 * HID] + rg * n0);
                float hv = (1.f - zg) * nn + zg * h0t[j * STRD + r];
                h0t[j * STRD + r] = hv;
            }
            {
                const float* gB = g_G0 + (size_t)toks[r + 1] * G3 + j;
                float rg = sigf(gB[0] + a1), zg = sigf(gB[HID] + z1);
                float nn = tanhf(gB[2 * HID] + rg * n1);
                float hv = (1.f - zg) * nn + zg * h0t[j * STRD + r + 1];
                h0t[j * STRD + r + 1] = hv;
            }
        }
        __syncthreads();   // new h0 tile complete

        // ---------- layer 1: gi1 = h0n @ W_ih1^T, gh1 = h1 @ W_hh1^T ----------
        // r,z gates merge across both GEMMs; n gate stays split (C=input, D=hidden)
#pragma unroll
        for (int u = 0; u < 8; u++) { A[u] = b1r; B[u] = b1z; C[u] = b1in; D[u] = b1hn; }
        if (rh == 0) {
            gemm3<4>(A, B, C, g_Wc1 + j, h0t, 0);
            gemm3<4>(A, B, D, g_Wc1 + (size_t)HID * HID + j, h1t, 0);
        } else {
            gemm3<3>(A, B, C, g_Wc1 + j, h0t, 4);
            gemm3<3>(A, B, D, g_Wc1 + (size_t)HID * HID + j, h1t, 4);
        }
        __syncthreads();   // all reads of old h1t done

        // epilogue 1 (update h1 tile, emit y)
#pragma unroll
        for (int u = 0; u < 8; u++) {
            if (u >= nu) break;
            float ra, rb2, za, zb, ia, ib, ma, mb;
            unpack2(A[u], ra, rb2); unpack2(B[u], za, zb);
            unpack2(C[u], ia, ib);  unpack2(D[u], ma, mb);
            int r = qb * 4 + 2 * u;
            {
                float rg = sigf(ra), zg = sigf(za);
                float nn = tanhf(ia + rg * ma);
                float hv = (1.f - zg) * nn + zg * h1t[j * STRD + r];
                h1t[j * STRD + r] = hv;
                int b = r0 + r;
                if (b < NB) g_y[((size_t)b * SEQ + t) * HID + j] = hv;
            }
            {
                float rg = sigf(rb2), zg = sigf(zb);
                float nn = tanhf(ib + rg * mb);
                float hv = (1.f - zg) * nn + zg * h1t[j * STRD + r + 1];
                h1t[j * STRD + r + 1] = hv;
                int b = r0 + r + 1;
                if (b < NB) g_y[((size_t)b * SEQ + t) * HID + j] = hv;
            }
        }
        __syncthreads();   // h1 tile complete before next step
    }
}

// ============================================================
// Fused projection: logits = relu(y @ W1^T + b1) @ W2^T + b2
// ============================================================
__global__ void __launch_bounds__(256) proj_k(const float* __restrict__ b1,
                                              const float* __restrict__ b2,
                                              float* __restrict__ out) {
    extern __shared__ float sm[];
    float* yt = sm;               // [k=256][PRB]
    float* ht = sm + HID * PRB;
    const int j = threadIdx.x;
    const size_t row0 = (size_t)blockIdx.x * PRB;

    for (int idx = j; idx < PRB * HID; idx += 256) {
        int r = idx >> 8, c = idx & (HID - 1);
        yt[c * PRB + r] = g_y[(row0 + r) * HID + c];
    }
    __syncthreads();

    // stage 1: hidden = relu(y @ W1^T + b1)
    {
        ull a[16];
        ull bb = pack2(b1[j], b1[j]);
#pragma unroll
        for (int u = 0; u < 16; u++) a[u] = bb;
#pragma unroll 2
        for (int k = 0; k < HID; k++) {
            float w = g_W1t[k * HID + j];
            ull wd = pack2(w, w);
            const ulonglong2* yp = (const ulonglong2*)(yt + k * PRB);
#pragma unroll
            for (int q = 0; q < 8; q++) {
                ulonglong2 y4 = yp[q];
                fma2(a[2 * q], y4.x, wd);
                fma2(a[2 * q + 1], y4.y, wd);
            }
        }
#pragma unroll
        for (int u = 0; u < 16; u++) {
            float lo, hi; unpack2(a[u], lo, hi);
            ht[j * PRB + 2 * u]     = fmaxf(lo, 0.f);
            ht[j * PRB + 2 * u + 1] = fmaxf(hi, 0.f);
        }
    }
    __syncthreads();

    // stage 2: logits = hidden @ W2^T + b2
    if (j < VOCAB) {
        ull a[16];
        ull bb = pack2(b2[j], b2[j]);
#pragma unroll
        for (int u = 0; u < 16; u++) a[u] = bb;
#pragma unroll 2
        for (int k = 0; k < HID; k++) {
            float w = g_W2t[k * VOCAB + j];
            ull wd = pack2(w, w);
            const ulonglong2* hp = (const ulonglong2*)(ht + k * PRB);
#pragma unroll
            for (int q = 0; q < 8; q++) {
                ulonglong2 h4 = hp[q];
                fma2(a[2 * q], h4.x, wd);
                fma2(a[2 * q + 1], h4.y, wd);
            }
        }
#pragma unroll
        for (int u = 0; u < 16; u++) {
            float lo, hi; unpack2(a[u], lo, hi);
            out[(row0 + 2 * u) * VOCAB + j]     = lo;
            out[(row0 + 2 * u + 1) * VOCAB + j] = hi;
        }
    }
}

// ---- generated = float(target_tokens[:, 1:]) ----
__global__ void gen_k(const int* __restrict__ tt, float* __restrict__ outg) {
    int i = blockIdx.x * blockDim.x + threadIdx.x;
    if (i < NB * SEQ) {
        int b = i / SEQ, s = i % SEQ;
        outg[i] = (float)tt[b * TLEN + 1 + s];
    }
}

extern "C" void kernel_launch(void* const* d_in, const int* in_sizes, int n_in,
                              void* d_out, int out_size) {
    const float* z    = (const float*)d_in[0];
    const int*   tt   = (const int*)  d_in[1];
    const float* emb  = (const float*)d_in[2];
    const float* Wlat = (const float*)d_in[3];
    const float* blat = (const float*)d_in[4];
    const float* Wih0 = (const float*)d_in[5];
    const float* Whh0 = (const float*)d_in[6];
    const float* bih0 = (const float*)d_in[7];
    const float* bhh0 = (const float*)d_in[8];
    const float* Wih1 = (const float*)d_in[9];
    const float* Whh1 = (const float*)d_in[10];
    const float* bih1 = (const float*)d_in[11];
    const float* bhh1 = (const float*)d_in[12];
    const float* W1   = (const float*)d_in[13];
    const float* b1   = (const float*)d_in[14];
    const float* W2   = (const float*)d_in[15];
    const float* b2   = (const float*)d_in[16];
    float* out = (float*)d_out;

    const int GRU_SMEM  = 2 * HID * STRD * sizeof(float);   // 65536
    const int PROJ_SMEM = 2 * HID * PRB * sizeof(float);    // 65536
    cudaFuncSetAttribute(gru_k,  cudaFuncAttributeMaxDynamicSharedMemorySize, GRU_SMEM);
    cudaFuncSetAttribute(proj_k, cudaFuncAttributeMaxDynamicSharedMemorySize, PROJ_SMEM);

    // 5 prep launches, then gru_k is launch #6 (ncu -s 5 -c 1 profiles it)
    hinit_k<<<dim3(NB, 2), 256>>>(z, Wlat, blat);
    g0_k<<<dim3(VOCAB, 3), 256>>>(emb, Wih0, bih0);
    trW12_k<<<dim3(HID, 2), HID>>>(W1, W2);
    packW0_k<<<HID, HID>>>(Whh0);
    packWc1_k<<<2 * HID, HID>>>(Wih1, Whh1);

    gru_k<<<GRID_G, 512, GRU_SMEM>>>(tt, bhh0, bih1, bhh1);

    proj_k<<<(NB * SEQ) / PRB, 256, PROJ_SMEM>>>(b1, b2, out);
    gen_k<<<(NB * SEQ + 255) / 256, 256>>>(tt, out + (size_t)NB * SEQ * VOCAB);
}

// round 4
// speedup vs baseline: 1.2961x; 1.0569x over previous
#include <cuda_runtime.h>

#define HID 256
#define G3 768
#define NB 8192
#define SEQ 49
#define TLEN 50
#define VOCAB 148
#define LATENT 32

#define RB 56         // rows per CTA (recurrence)
#define HALF 28       // rows per thread-half
#define NP 14         // packed row-pairs per half
#define NQ2 7         // ulonglong2 loads per half
#define STRD 56       // floats per k-row in SMEM tile
#define GRID_G 147    // 147*56 = 8232 >= 8192, one wave
#define PRB 32        // rows per CTA (projection)

typedef unsigned long long ull;

// ---- scratch (__device__ globals: allocation-free) ----
__device__ float g_h0[NB * HID];
__device__ float g_h1[NB * HID];
__device__ float g_y[(size_t)NB * SEQ * HID];
__device__ float g_G0[VOCAB * G3];
__device__ float4 g_W0p[HID * HID];        // layer0: [k][j] = (wr, wz, wn, 0)
__device__ float  g_W1r[2 * HID * HID];    // layer1 r-gate: [kk][j], kk<256 -> Wih1_r, else Whh1_r
__device__ float2 g_W1s2[2 * HID * HID];   // layer1 stage2: [kk][j] = (w_z, w_n)
__device__ float  g_W1t[HID * HID];        // [k][o]
__device__ float  g_W2t[HID * VOCAB];      // [k][v]

__device__ __forceinline__ float sigf(float x) { return 1.f / (1.f + expf(-x)); }

__device__ __forceinline__ ull pack2(float lo, float hi) {
    ull r; asm("mov.b64 %0, {%1,%2};" : "=l"(r) : "f"(lo), "f"(hi)); return r;
}
__device__ __forceinline__ void unpack2(ull v, float& lo, float& hi) {
    asm("mov.b64 {%0,%1}, %2;" : "=f"(lo), "=f"(hi) : "l"(v));
}
__device__ __forceinline__ void fma2(ull& acc, ull a, ull b) {
    asm("fma.rn.f32x2 %0, %1, %2, %0;" : "+l"(acc) : "l"(a), "l"(b));
}

// ============================================================
// Prep (3 launches; gru_k is our 4th launch -> ncu profiles it)
// ============================================================

// 1) h init: h[b, 2*HID] = z @ W_lat^T + b_lat
__global__ void hinit_k(const float* __restrict__ z, const float* __restrict__ Wlat,
                        const float* __restrict__ blat) {
    int b = blockIdx.x;
    int j = blockIdx.y * blockDim.x + threadIdx.x;  // 0..511
    __shared__ float zs[LATENT];
    if (threadIdx.x < LATENT) zs[threadIdx.x] = z[b * LATENT + threadIdx.x];
    __syncthreads();
    float acc = blat[j];
    const float* w = Wlat + (size_t)j * LATENT;
#pragma unroll
    for (int k = 0; k < LATENT; k++) acc = fmaf(zs[k], w[k], acc);
    if (j < HID) g_h0[(size_t)b * HID + j] = acc;
    else         g_h1[(size_t)b * HID + (j - HID)] = acc;
}

// 2) G0[v, 768] = emb[v] @ W_ih0^T + b_ih0
__global__ void g0_k(const float* __restrict__ emb, const float* __restrict__ Wih0,
                     const float* __restrict__ bih0) {
    int v = blockIdx.x;
    int g = blockIdx.y * blockDim.x + threadIdx.x;  // 0..767
    __shared__ float es[HID];
    es[threadIdx.x] = emb[v * HID + threadIdx.x];
    __syncthreads();
    float acc = bih0[g];
    const float* w = Wih0 + (size_t)g * HID;
#pragma unroll 4
    for (int k = 0; k < HID; k++) acc = fmaf(es[k], w[k], acc);
    g_G0[v * G3 + g] = acc;
}

// 3) all weight packing in one launch
__global__ void pack_all(const float* __restrict__ Whh0, const float* __restrict__ Wih1,
                         const float* __restrict__ Whh1, const float* __restrict__ W1,
                         const float* __restrict__ W2) {
    int i = blockIdx.x;     // 0..255
    int j = threadIdx.x;    // 0..255
    int task = blockIdx.y;
    if (task == 0) {
        g_W0p[i * HID + j] = make_float4(Whh0[(size_t)j * HID + i],
                                         Whh0[(size_t)(HID + j) * HID + i],
                                         Whh0[(size_t)(2 * HID + j) * HID + i], 0.f);
    } else if (task == 1) {
        g_W1r[i * HID + j]         = Wih1[(size_t)j * HID + i];
        g_W1r[(HID + i) * HID + j] = Whh1[(size_t)j * HID + i];
    } else if (task == 2) {
        g_W1s2[i * HID + j] = make_float2(Wih1[(size_t)(HID + j) * HID + i],
                                          Wih1[(size_t)(2 * HID + j) * HID + i]);
        g_W1s2[(HID + i) * HID + j] = make_float2(Whh1[(size_t)(HID + j) * HID + i],
                                                  Whh1[(size_t)(2 * HID + j) * HID + i]);
    } else {
        g_W1t[i * HID + j] = W1[(size_t)j * HID + i];
        if (j < VOCAB) g_W2t[i * VOCAB + j] = W2[(size_t)j * HID + i];
    }
}

// ============================================================
// Persistent GRU recurrence: 147 CTAs (one wave), RB=56
// ============================================================
__global__ void __launch_bounds__(512) gru_k(const int* __restrict__ tt,
                                             const float* __restrict__ bhh0,
                                             const float* __restrict__ bih1,
                                             const float* __restrict__ bhh1) {
    extern __shared__ float sm[];
    float* h0t = sm;                       // [k=256][STRD]
    float* h1t = sm + HID * STRD;
    float* rgs = sm + 2 * HID * STRD;      // [56][256] r-gate values
    __shared__ int toks[RB];

    const int tid  = threadIdx.x;
    const int j    = tid & (HID - 1);      // column 0..255
    const int rh   = tid >> 8;             // row-half
    const int roff = rh * HALF;
    const int qoff = rh * NQ2;             // ulonglong2 offset
    const int r0   = blockIdx.x * RB;

    // biases
    const float c0r = bhh0[j], c0z = bhh0[HID + j], c0n = bhh0[2 * HID + j];
    const float c1r = bih1[j] + bhh1[j];
    const float c1z = bih1[HID + j] + bhh1[HID + j];
    const float c1i = bih1[2 * HID + j];
    const float c1h = bhh1[2 * HID + j];

    // load initial h tiles
    for (int idx = tid; idx < RB * HID; idx += 512) {
        int r = idx >> 8, c = idx & (HID - 1);
        int bc = min(r0 + r, NB - 1);
        h0t[c * STRD + r] = g_h0[(size_t)bc * HID + c];
        h1t[c * STRD + r] = g_h1[(size_t)bc * HID + c];
    }
    __syncthreads();

    for (int t = 0; t < SEQ; t++) {
        if (tid < RB) toks[tid] = t ? tt[min(r0 + tid, NB - 1) * TLEN + t] : 1;

        // ---------- layer 0: gh0 = h0 @ W_hh0^T (3 gates) ----------
        {
            ull Ar[NP], Az[NP], An[NP];
            ull pr = pack2(c0r, c0r), pz = pack2(c0z, c0z), pn = pack2(c0n, c0n);
#pragma unroll
            for (int u = 0; u < NP; u++) { Ar[u] = pr; Az[u] = pz; An[u] = pn; }
#pragma unroll 2
            for (int k = 0; k < HID; k++) {
                float4 w = g_W0p[k * HID + j];
                ull w0 = pack2(w.x, w.x), w1 = pack2(w.y, w.y), w2 = pack2(w.z, w.z);
                const ulonglong2* hp = (const ulonglong2*)(h0t + k * STRD) + qoff;
#pragma unroll
                for (int q = 0; q < NQ2; q++) {
                    ulonglong2 h4 = hp[q];
                    fma2(Ar[2 * q], h4.x, w0); fma2(Ar[2 * q + 1], h4.y, w0);
                    fma2(Az[2 * q], h4.x, w1); fma2(Az[2 * q + 1], h4.y, w1);
                    fma2(An[2 * q], h4.x, w2); fma2(An[2 * q + 1], h4.y, w2);
                }
            }
            __syncthreads();   // gemm reads done; toks visible
#pragma unroll
            for (int u = 0; u < NP; u++) {
                float a0, a1, z0, z1, n0, n1;
                unpack2(Ar[u], a0, a1); unpack2(Az[u], z0, z1); unpack2(An[u], n0, n1);
                int r = roff + 2 * u;
                const float* gA = g_G0 + (size_t)toks[r] * G3 + j;
                const float* gB = g_G0 + (size_t)toks[r + 1] * G3 + j;
                float rg = sigf(gA[0] + a0), zg = sigf(gA[HID] + z0);
                float nn = tanhf(gA[2 * HID] + rg * n0);
                h0t[j * STRD + r] = (1.f - zg) * nn + zg * h0t[j * STRD + r];
                rg = sigf(gB[0] + a1); zg = sigf(gB[HID] + z1);
                nn = tanhf(gB[2 * HID] + rg * n1);
                h0t[j * STRD + r + 1] = (1.f - zg) * nn + zg * h0t[j * STRD + r + 1];
            }
            __syncthreads();   // new h0 tile complete
        }

        // ---------- layer 1, stage 1: r gate over merged K=512 ----------
        {
            ull R[NP];
            ull pr = pack2(c1r, c1r);
#pragma unroll
            for (int u = 0; u < NP; u++) R[u] = pr;
#pragma unroll 4
            for (int k = 0; k < HID; k++) {
                float w = g_W1r[k * HID + j];
                ull wd = pack2(w, w);
                const ulonglong2* hp = (const ulonglong2*)(h0t + k * STRD) + qoff;
#pragma unroll
                for (int q = 0; q < NQ2; q++) {
                    ulonglong2 h4 = hp[q];
                    fma2(R[2 * q], h4.x, wd); fma2(R[2 * q + 1], h4.y, wd);
                }
            }
#pragma unroll 4
            for (int k = 0; k < HID; k++) {
                float w = g_W1r[(HID + k) * HID + j];
                ull wd = pack2(w, w);
                const ulonglong2* hp = (const ulonglong2*)(h1t + k * STRD) + qoff;
#pragma unroll
                for (int q = 0; q < NQ2; q++) {
                    ulonglong2 h4 = hp[q];
                    fma2(R[2 * q], h4.x, wd); fma2(R[2 * q + 1], h4.y, wd);
                }
            }
            // same-thread readback later -> no barrier needed
#pragma unroll
            for (int u = 0; u < NP; u++) {
                float lo, hi; unpack2(R[u], lo, hi);
                int r = roff + 2 * u;
                rgs[r * HID + j]       = sigf(lo);
                rgs[(r + 1) * HID + j] = sigf(hi);
            }
        }

        // ---------- layer 1, stage 2: z (merged), i_n, h_n ----------
        {
            ull Z[NP], In[NP], Hn[NP];
            ull pz = pack2(c1z, c1z), pi = pack2(c1i, c1i), ph = pack2(c1h, c1h);
#pragma unroll
            for (int u = 0; u < NP; u++) { Z[u] = pz; In[u] = pi; Hn[u] = ph; }
#pragma unroll 2
            for (int k = 0; k < HID; k++) {
                float2 w = g_W1s2[k * HID + j];
                ull wz = pack2(w.x, w.x), wn = pack2(w.y, w.y);
                const ulonglong2* hp = (const ulonglong2*)(h0t + k * STRD) + qoff;
#pragma unroll
                for (int q = 0; q < NQ2; q++) {
                    ulonglong2 h4 = hp[q];
                    fma2(Z[2 * q], h4.x, wz);  fma2(Z[2 * q + 1], h4.y, wz);
                    fma2(In[2 * q], h4.x, wn); fma2(In[2 * q + 1], h4.y, wn);
                }
            }
#pragma unroll 2
            for (int k = 0; k < HID; k++) {
                float2 w = g_W1s2[(HID + k) * HID + j];
                ull wz = pack2(w.x, w.x), wn = pack2(w.y, w.y);
                const ulonglong2* hp = (const ulonglong2*)(h1t + k * STRD) + qoff;
#pragma unroll
                for (int q = 0; q < NQ2; q++) {
                    ulonglong2 h4 = hp[q];
                    fma2(Z[2 * q], h4.x, wz);  fma2(Z[2 * q + 1], h4.y, wz);
                    fma2(Hn[2 * q], h4.x, wn); fma2(Hn[2 * q + 1], h4.y, wn);
                }
            }
            __syncthreads();   // all h1t reads done
#pragma unroll
            for (int u = 0; u < NP; u++) {
                float z0, z1, i0, i1, m0, m1;
                unpack2(Z[u], z0, z1); unpack2(In[u], i0, i1); unpack2(Hn[u], m0, m1);
                int r = roff + 2 * u;
                {
                    float rg = rgs[r * HID + j];
                    float zg = sigf(z0);
                    float nn = tanhf(i0 + rg * m0);
                    float hv = (1.f - zg) * nn + zg * h1t[j * STRD + r];
                    h1t[j * STRD + r] = hv;
                    int b = r0 + r;
                    if (b < NB) g_y[((size_t)b * SEQ + t) * HID + j] = hv;
                }
                {
                    float rg = rgs[(r + 1) * HID + j];
                    float zg = sigf(z1);
                    float nn = tanhf(i1 + rg * m1);
                    float hv = (1.f - zg) * nn + zg * h1t[j * STRD + r + 1];
                    h1t[j * STRD + r + 1] = hv;
                    int b = r0 + r + 1;
                    if (b < NB) g_y[((size_t)b * SEQ + t) * HID + j] = hv;
                }
            }
            __syncthreads();   // step complete
        }
    }
}

// ============================================================
// Fused projection: logits = relu(y @ W1^T + b1) @ W2^T + b2
// ============================================================
__global__ void __launch_bounds__(256) proj_k(const float* __restrict__ b1,
                                              const float* __restrict__ b2,
                                              float* __restrict__ out) {
    extern __shared__ float sm[];
    float* yt = sm;               // [k=256][PRB]
    float* ht = sm + HID * PRB;
    const int j = threadIdx.x;
    const size_t row0 = (size_t)blockIdx.x * PRB;

    for (int idx = j; idx < PRB * HID; idx += 256) {
        int r = idx >> 8, c = idx & (HID - 1);
        yt[c * PRB + r] = g_y[(row0 + r) * HID + c];
    }
    __syncthreads();

    {
        ull a[16];
        ull bb = pack2(b1[j], b1[j]);
#pragma unroll
        for (int u = 0; u < 16; u++) a[u] = bb;
#pragma unroll 2
        for (int k = 0; k < HID; k++) {
            float w = g_W1t[k * HID + j];
            ull wd = pack2(w, w);
            const ulonglong2* yp = (const ulonglong2*)(yt + k * PRB);
#pragma unroll
            for (int q = 0; q < 8; q++) {
                ulonglong2 y4 = yp[q];
                fma2(a[2 * q], y4.x, wd);
                fma2(a[2 * q + 1], y4.y, wd);
            }
        }
#pragma unroll
        for (int u = 0; u < 16; u++) {
            float lo, hi; unpack2(a[u], lo, hi);
            ht[j * PRB + 2 * u]     = fmaxf(lo, 0.f);
            ht[j * PRB + 2 * u + 1] = fmaxf(hi, 0.f);
        }
    }
    __syncthreads();

    if (j < VOCAB) {
        ull a[16];
        ull bb = pack2(b2[j], b2[j]);
#pragma unroll
        for (int u = 0; u < 16; u++) a[u] = bb;
#pragma unroll 2
        for (int k = 0; k < HID; k++) {
            float w = g_W2t[k * VOCAB + j];
            ull wd = pack2(w, w);
            const ulonglong2* hp = (const ulonglong2*)(ht + k * PRB);
#pragma unroll
            for (int q = 0; q < 8; q++) {
                ulonglong2 h4 = hp[q];
                fma2(a[2 * q], h4.x, wd);
                fma2(a[2 * q + 1], h4.y, wd);
            }
        }
#pragma unroll
        for (int u = 0; u < 16; u++) {
            float lo, hi; unpack2(a[u], lo, hi);
            out[(row0 + 2 * u) * VOCAB + j]     = lo;
            out[(row0 + 2 * u + 1) * VOCAB + j] = hi;
        }
    }
}

// ---- generated = float(target_tokens[:, 1:]) ----
__global__ void gen_k(const int* __restrict__ tt, float* __restrict__ outg) {
    int i = blockIdx.x * blockDim.x + threadIdx.x;
    if (i < NB * SEQ) {
        int b = i / SEQ, s = i % SEQ;
        outg[i] = (float)tt[b * TLEN + 1 + s];
    }
}

extern "C" void kernel_launch(void* const* d_in, const int* in_sizes, int n_in,
                              void* d_out, int out_size) {
    const float* z    = (const float*)d_in[0];
    const int*   tt   = (const int*)  d_in[1];
    const float* emb  = (const float*)d_in[2];
    const float* Wlat = (const float*)d_in[3];
    const float* blat = (const float*)d_in[4];
    const float* Wih0 = (const float*)d_in[5];
    const float* Whh0 = (const float*)d_in[6];
    const float* bih0 = (const float*)d_in[7];
    const float* bhh0 = (const float*)d_in[8];
    const float* Wih1 = (const float*)d_in[9];
    const float* Whh1 = (const float*)d_in[10];
    const float* bih1 = (const float*)d_in[11];
    const float* bhh1 = (const float*)d_in[12];
    const float* W1   = (const float*)d_in[13];
    const float* b1   = (const float*)d_in[14];
    const float* W2   = (const float*)d_in[15];
    const float* b2   = (const float*)d_in[16];
    float* out = (float*)d_out;

    const int GRU_SMEM  = (2 * HID * STRD + RB * HID) * sizeof(float);  // 172 KB
    const int PROJ_SMEM = 2 * HID * PRB * sizeof(float);                // 64 KB
    cudaFuncSetAttribute(gru_k,  cudaFuncAttributeMaxDynamicSharedMemorySize, GRU_SMEM);
    cudaFuncSetAttribute(proj_k, cudaFuncAttributeMaxDynamicSharedMemorySize, PROJ_SMEM);

    hinit_k<<<dim3(NB, 2), 256>>>(z, Wlat, blat);
    g0_k<<<dim3(VOCAB, 3), 256>>>(emb, Wih0, bih0);
    pack_all<<<dim3(HID, 4), HID>>>(Whh0, Wih1, Whh1, W1, W2);

    gru_k<<<GRID_G, 512, GRU_SMEM>>>(tt, bhh0, bih1, bhh1);   // our 4th launch

    proj_k<<<(NB * SEQ) / PRB, 256, PROJ_SMEM>>>(b1, b2, out);
    gen_k<<<(NB * SEQ + 255) / 256, 256>>>(tt, out + (size_t)NB * SEQ * VOCAB);
}